// round 2
// baseline (speedup 1.0000x reference)
#include <cuda_runtime.h>
#include <cuda_bf16.h>

// emb[b,f,e] = b2[f,e] + sum_h W2[f,e,h]*relu(x[b,f]*W1[f,h]+b1[f,h])
// Piecewise-linear-in-x: per f, 65 segments; emb = A(seg)*x + C(seg).
// Segment table row (128B): 8 x float4 (A_{2j}, A_{2j+1}, C_{2j}, C_{2j+1}).

#define BN 16384
#define FN 128
#define HN 64
#define EN 16

#define BUCK_LO (-6.0f)
#define BUCK_SC (256.0f / 12.0f)

__device__ float  g_tabflat[FN * 65 * 32];   // per f: 65 segs * 32 floats (128B rows)
__device__ float  g_thr[FN * 64];
__device__ uchar2 g_lutp[FN * 257];          // (lut[k], lut[k+1]) pairs

__device__ __forceinline__ int bucket_of(float v) {
    float p = (v - BUCK_LO) * BUCK_SC;
    p = fminf(fmaxf(p, 0.0f), 255.0f);
    return (int)p;
}

// ---------------------------------------------------------------------------
// Kernel 1: per-feature precompute. One block per f, 128 threads.
// ---------------------------------------------------------------------------
__global__ void __launch_bounds__(128) dfe_precompute(
    const float* __restrict__ W1, const float* __restrict__ b1,
    const float* __restrict__ W2, const float* __restrict__ b2)
{
    int f = blockIdx.x;
    int tid = threadIdx.x;

    __shared__ float sw[HN], sb[HN], tv_[HN], st[HN];
    __shared__ int   sidx[HN];
    __shared__ float stab[65 * 32];

    if (tid < HN) {
        float w = W1[f * HN + tid];
        float b = b1[f * HN + tid];
        sw[tid] = w; sb[tid] = b;
        tv_[tid] = (w != 0.0f) ? (-b / w) : 3.0e38f;  // sentinel never crossed
    }
    __syncthreads();

    // stable rank-sort of 64 thresholds
    if (tid < HN) {
        float tv = tv_[tid];
        int r = 0;
        for (int j = 0; j < HN; j++) {
            float tj = tv_[j];
            r += (tj < tv) || (tj == tv && j < tid);
        }
        st[r] = tv;
        sidx[r] = tid;
    }
    __syncthreads();

    if (tid < HN) g_thr[f * HN + tid] = st[tid];

    // lut pairs: lut[k] = #{ thr with bucket < k }
    for (int k = tid; k < 257; k += blockDim.x) {
        int c0 = 0, c1 = 0;
        for (int j = 0; j < HN; j++) {
            int bk = bucket_of(st[j]);
            c0 += (bk < k);
            c1 += (bk <= k);
        }
        g_lutp[f * 257 + k] = make_uchar2((unsigned char)c0, (unsigned char)c1);
    }

    // segment walk: 16 threads, one per e
    if (tid < EN) {
        int e = tid;
        const float* w2 = W2 + (f * EN + e) * HN;
        float A = 0.0f;
        float C = b2[f * EN + e];
        for (int h = 0; h < HN; h++) {
            float w = sw[h], b = sb[h], v = w2[h];
            if (w < 0.0f)       { A += w * v; C += b * v; }
            else if (w == 0.0f) { C += fmaxf(b, 0.0f) * v; }
        }
        int grp = e >> 1, par = e & 1;
        for (int s = 0; s <= 64; s++) {
            stab[s * 32 + grp * 4 + par]     = A;   // A_e
            stab[s * 32 + grp * 4 + 2 + par] = C;   // C_e
            if (s < 64) {
                int h = sidx[s];
                float w = sw[h], b = sb[h], v = w2[h];
                if (w > 0.0f)      { A += w * v; C += b * v; }
                else if (w < 0.0f) { A -= w * v; C -= b * v; }
            }
        }
    }
    __syncthreads();

    // coalesced table writeback
    const float4* src = (const float4*)stab;
    float4* dst = (float4*)(g_tabflat + f * 2080);
    for (int i = tid; i < 520; i += 128) dst[i] = src[i];
}

// ---------------------------------------------------------------------------
// Kernel 2: evaluation. Block = 4 features ("quad") x 512 batch rows.
// 256 threads = 8 warps; warp w owns rows [w*64, w*64+64); warp = 1 row x 4 f.
// Lane: ff = lane>>3 (feature in quad), j = lane&7 (e-pair). No barriers in loop.
// ---------------------------------------------------------------------------
__global__ void __launch_bounds__(256) dfe_eval(
    const float* __restrict__ x, float* __restrict__ out)
{
    __shared__ float4 stab4[4 * 520];     // 4 feature tables, 128B-aligned seg rows
    __shared__ float  sthr[4 * 64];
    __shared__ uchar2 slut[4 * 260];      // padded stride

    int tid  = threadIdx.x;
    int quad = blockIdx.x;                // feature quad: f = quad*4 + ff
    int bbase = blockIdx.y * 512;

    {
        const float4* gsrc = (const float4*)(g_tabflat + quad * 4 * 2080);
        for (int i = tid; i < 4 * 520; i += 256) stab4[i] = gsrc[i];
        for (int i = tid; i < 256; i += 256) sthr[i] = g_thr[quad * 256 + i];
        for (int i = tid; i < 4 * 257; i += 256) {
            int ff = i / 257, k = i % 257;
            slut[ff * 260 + k] = g_lutp[(quad * 4 + ff) * 257 + k];
        }
    }
    __syncthreads();

    int w = tid >> 5, lane = tid & 31;
    int ff = lane >> 3, j = lane & 7;

    const float*  xp   = x + (size_t)(bbase + w * 64) * FN + quad * 4 + ff;
    float*        op   = out + (size_t)(bbase + w * 64) * (FN * EN) + quad * 64 + ff * 16 + j * 2;
    const float*  thrf = sthr + ff * 64;
    const uchar2* lutf = slut + ff * 260;
    const float4* tabf = stab4 + ff * 520;

    float xs_next = __ldcs(xp);
    #pragma unroll 2
    for (int it = 0; it < 64; it++) {
        float xs = xs_next;
        if (it + 1 < 64) xs_next = __ldcs(xp + (size_t)(it + 1) * FN);

        int k = bucket_of(xs);
        uchar2 p = lutf[k];
        int seg = p.x;
        for (int t = p.x; t < p.y; t++) seg += (thrf[t] <= xs);

        float4 v = tabf[seg * 8 + j];
        float2 o;
        o.x = fmaf(v.x, xs, v.z);
        o.y = fmaf(v.y, xs, v.w);
        *(float2*)(op + (size_t)it * (FN * EN)) = o;
    }
}

extern "C" void kernel_launch(void* const* d_in, const int* in_sizes, int n_in,
                              void* d_out, int out_size)
{
    const float* x  = (const float*)d_in[0];
    const float* W1 = (const float*)d_in[1];
    const float* b1 = (const float*)d_in[2];
    const float* W2 = (const float*)d_in[3];
    const float* b2 = (const float*)d_in[4];
    float* out = (float*)d_out;

    dfe_precompute<<<FN, 128>>>(W1, b1, W2, b2);
    dfe_eval<<<dim3(FN / 4, BN / 512), 256>>>(x, out);
}

// round 4
// speedup vs baseline: 2.1798x; 2.1798x over previous
#include <cuda_runtime.h>
#include <cuda_bf16.h>

// emb[b,f,e] = b2[f,e] + sum_h W2[f,e,h]*relu(x[b,f]*W1[f,h]+b1[f,h])
// Piecewise-linear-in-x: per f, 65 segments; emb = A(seg)*x + C(seg).
// Segment row (128B): 8 x float4 (A_{2j}, A_{2j+1}, C_{2j}, C_{2j+1}).

#define BN 16384
#define FN 128
#define HN 64
#define EN 16
#define THR_S 72   // padded stride so the 4 per-feature threshold arrays hit distinct banks

__device__ float g_tabflat[FN * 65 * 32];   // per f: 65 segs * 32 floats (128B rows)
__device__ float g_thr[FN * 64];            // sorted hinge thresholds per f

// ---------------------------------------------------------------------------
// Kernel 1: per-feature precompute. One block per f, 128 threads.
// ---------------------------------------------------------------------------
__global__ void __launch_bounds__(128) dfe_precompute(
    const float* __restrict__ W1, const float* __restrict__ b1,
    const float* __restrict__ W2, const float* __restrict__ b2)
{
    int f = blockIdx.x;
    int tid = threadIdx.x;

    __shared__ float sw[HN], sb[HN], tv_[HN], st[HN];
    __shared__ int   sidx[HN];
    __shared__ float sv[EN * HN];      // W2 row staged in smem (kills 65 serial LDGs)
    __shared__ float stab[65 * 32];

    for (int i = tid; i < EN * HN; i += 128) sv[i] = W2[f * EN * HN + i];

    if (tid < HN) {
        float w = W1[f * HN + tid];
        float b = b1[f * HN + tid];
        sw[tid] = w; sb[tid] = b;
        tv_[tid] = (w != 0.0f) ? (-b / w) : 3.0e38f;  // sentinel: never crossed
    }
    __syncthreads();

    // stable rank-sort of 64 thresholds
    if (tid < HN) {
        float tv = tv_[tid];
        int r = 0;
        for (int j = 0; j < HN; j++) {
            float tj = tv_[j];
            r += (tj < tv) || (tj == tv && j < tid);
        }
        st[r] = tv;
        sidx[r] = tid;
    }
    __syncthreads();

    if (tid < HN) g_thr[f * HN + tid] = st[tid];

    // segment walk: 16 threads, one per e (all operands in smem)
    if (tid < EN) {
        int e = tid;
        const float* w2 = sv + e * HN;
        float A = 0.0f;
        float C = b2[f * EN + e];
        for (int h = 0; h < HN; h++) {
            float w = sw[h], b = sb[h], v = w2[h];
            float m = (w < 0.0f) ? 1.0f : 0.0f;        // active at x = -inf
            A += m * w * v;
            C += m * b * v;
            C += (w == 0.0f) ? fmaxf(b, 0.0f) * v : 0.0f;  // constant hinge
        }
        int grp = e >> 1, par = e & 1;
        for (int s = 0; s <= 64; s++) {
            stab[s * 32 + grp * 4 + par]     = A;   // A_e
            stab[s * 32 + grp * 4 + 2 + par] = C;   // C_e
            if (s < 64) {
                int h = sidx[s];
                float w = sw[h], b = sb[h], v = w2[h];
                float sg = (w > 0.0f) ? 1.0f : ((w < 0.0f) ? -1.0f : 0.0f);
                A += sg * w * v;   // w>0: turns ON; w<0: turns OFF
                C += sg * b * v;
            }
        }
    }
    __syncthreads();

    // coalesced table writeback
    const float4* src = (const float4*)stab;
    float4* dst = (float4*)(g_tabflat + f * 2080);
    for (int i = tid; i < 520; i += 128) dst[i] = src[i];
}

// ---------------------------------------------------------------------------
// Branch-free count of { thr[t] <= xs } over 64 sorted entries (7 LDS).
// ---------------------------------------------------------------------------
__device__ __forceinline__ int seg_search(const float* __restrict__ thrp, float xs)
{
    int p = (thrp[31] <= xs) ? 32 : 0;
    p += (thrp[p + 15] <= xs) ? 16 : 0;
    p += (thrp[p + 7]  <= xs) ? 8  : 0;
    p += (thrp[p + 3]  <= xs) ? 4  : 0;
    p += (thrp[p + 1]  <= xs) ? 2  : 0;
    p += (thrp[p]      <= xs) ? 1  : 0;
    return p + ((thrp[p] <= xs) ? 1 : 0);   // count in [0,64]
}

// ---------------------------------------------------------------------------
// Kernel 2: evaluation. Block = 4 features ("quad") x 512 rows, 256 threads.
// Warp owns 64 rows, processed as 8 batches of 8 rows.
// Phase 1: lane = (row = lane&7, ff = lane>>3) -> 32 distinct searches.
// Phase 2: lane = (ff = lane>>3, j = lane&7); seg/x redistributed via shfl;
//          8 independent LDS.128 -> 2xFMA -> coalesced 256B stcs per batch.
// No barriers / no staging in the main loop; next search pipelined over phase 2.
// ---------------------------------------------------------------------------
__global__ void __launch_bounds__(256) dfe_eval(
    const float* __restrict__ x, float* __restrict__ out)
{
    __shared__ float4 stab[4 * 520];
    __shared__ float  sthr[4 * THR_S];

    int tid = threadIdx.x;
    int quad = blockIdx.x;
    int bbase = blockIdx.y * 512;

    {
        const float4* gsrc = (const float4*)(g_tabflat + quad * 4 * 2080);
        for (int i = tid; i < 4 * 520; i += 256) stab[i] = gsrc[i];
        for (int i = tid; i < 4 * 64; i += 256)
            sthr[(i >> 6) * THR_S + (i & 63)] = g_thr[quad * 256 + i];
    }
    __syncthreads();

    int lane = tid & 31, w = tid >> 5;
    int rrow = lane & 7;        // phase-1 row within batch
    int ff   = lane >> 3;       // feature within quad (both phases)
    int j    = lane & 7;        // phase-2 e-pair

    const float*  thrp = sthr + ff * THR_S;
    const float4* tabf = stab + ff * 520;

    int rb0 = bbase + w * 64;
    const float* xpb  = x   + (size_t)rb0 * FN + quad * 4 + ff;
    float*       outb = out + (size_t)rb0 * (FN * EN) + quad * 64 + ff * 16 + j * 2;

    float xs = __ldg(xpb + (size_t)rrow * FN);
    int   seg = seg_search(thrp, xs);

    #pragma unroll
    for (int batch = 0; batch < 8; batch++) {
        float xs_c  = xs;
        int   seg_c = seg;
        if (batch < 7) {   // pipeline: next batch's load+search over current phase 2
            xs  = __ldg(xpb + (size_t)((batch + 1) * 8 + rrow) * FN);
            seg = seg_search(thrp, xs);
        }

        float* orow = outb + (size_t)(batch * 8) * (FN * EN);
        #pragma unroll
        for (int r2 = 0; r2 < 8; r2++) {
            int src = (lane & 24) | r2;                    // lane holding (row=r2, ff)
            float xb  = __shfl_sync(0xffffffffu, xs_c,  src);
            int   sg  = __shfl_sync(0xffffffffu, seg_c, src);
            float4 v = tabf[sg * 8 + j];
            float2 o;
            o.x = fmaf(v.x, xb, v.z);
            o.y = fmaf(v.y, xb, v.w);
            __stcs((float2*)(orow + (size_t)r2 * (FN * EN)), o);
        }
    }
}

extern "C" void kernel_launch(void* const* d_in, const int* in_sizes, int n_in,
                              void* d_out, int out_size)
{
    const float* x  = (const float*)d_in[0];
    const float* W1 = (const float*)d_in[1];
    const float* b1 = (const float*)d_in[2];
    const float* W2 = (const float*)d_in[3];
    const float* b2 = (const float*)d_in[4];
    float* out = (float*)d_out;

    dfe_precompute<<<FN, 128>>>(W1, b1, W2, b2);
    dfe_eval<<<dim3(FN / 4, BN / 512), 256>>>(x, out);
}

// round 5
// speedup vs baseline: 2.3162x; 1.0626x over previous
#include <cuda_runtime.h>
#include <cuda_bf16.h>
#include <cuda_fp16.h>

// emb[b,f,e] = b2[f,e] + sum_h W2[f,e,h]*relu(x[b,f]*W1[f,h]+b1[f,h])
// Piecewise-linear-in-x: per f, 65 segments; emb = A(seg)*x + C(seg).
// fp16 segment row (64B): 8 x {half2 A, half2 C}.

#define BN 16384
#define FN 128
#define HN 64
#define EN 16
#define THR_S 72        // threshold array stride (word-bank spread 0/8/16/24)
#define TAB_S 524       // smem table stride in h4 units (padding decorrelates parity)

struct __align__(8) h4 { __half2 a, c; };

__device__ h4    g_tab_h[FN * 520];   // per f: 65 segs * 8 h4
__device__ float g_thr[FN * 64];      // sorted hinge thresholds per f

// ---------------------------------------------------------------------------
// Kernel 1: per-feature precompute. One block per f, 128 threads.
// ---------------------------------------------------------------------------
__global__ void __launch_bounds__(128) dfe_precompute(
    const float* __restrict__ W1, const float* __restrict__ b1,
    const float* __restrict__ W2, const float* __restrict__ b2)
{
    int f = blockIdx.x;
    int tid = threadIdx.x;

    __shared__ float sw[HN], sb[HN], tv_[HN], st[HN];
    __shared__ int   sidx[HN];
    __shared__ float sv[EN * HN];      // W2 row staged (kills serial LDGs in walk)
    __shared__ float stab[65 * 32];

    for (int i = tid; i < EN * HN; i += 128) sv[i] = W2[f * EN * HN + i];

    if (tid < HN) {
        float w = W1[f * HN + tid];
        float b = b1[f * HN + tid];
        sw[tid] = w; sb[tid] = b;
        tv_[tid] = (w != 0.0f) ? (-b / w) : 3.0e38f;  // sentinel: never crossed
    }
    __syncthreads();

    // stable rank-sort of 64 thresholds
    if (tid < HN) {
        float tv = tv_[tid];
        int r = 0;
        for (int j = 0; j < HN; j++) {
            float tj = tv_[j];
            r += (tj < tv) || (tj == tv && j < tid);
        }
        st[r] = tv;
        sidx[r] = tid;
    }
    __syncthreads();

    if (tid < HN) g_thr[f * HN + tid] = st[tid];

    // segment walk: 16 threads, one per e (all operands in smem)
    if (tid < EN) {
        int e = tid;
        const float* w2 = sv + e * HN;
        float A = 0.0f;
        float C = b2[f * EN + e];
        for (int h = 0; h < HN; h++) {
            float w = sw[h], b = sb[h], v = w2[h];
            float m = (w < 0.0f) ? 1.0f : 0.0f;            // active at x=-inf
            A += m * w * v;
            C += m * b * v;
            C += (w == 0.0f) ? fmaxf(b, 0.0f) * v : 0.0f;  // constant hinge
        }
        int grp = e >> 1, par = e & 1;
        for (int s = 0; s <= 64; s++) {
            stab[s * 32 + grp * 4 + par]     = A;
            stab[s * 32 + grp * 4 + 2 + par] = C;
            if (s < 64) {
                int h = sidx[s];
                float w = sw[h], b = sb[h], v = w2[h];
                float sg = (w > 0.0f) ? 1.0f : ((w < 0.0f) ? -1.0f : 0.0f);
                A += sg * w * v;
                C += sg * b * v;
            }
        }
    }
    __syncthreads();

    // pack fp32 staging -> fp16 table, coalesced writeback
    for (int i = tid; i < 520; i += 128) {
        int s = i >> 3, j = i & 7;
        const float* p = stab + s * 32 + j * 4;
        h4 v;
        v.a = __floats2half2_rn(p[0], p[1]);
        v.c = __floats2half2_rn(p[2], p[3]);
        g_tab_h[f * 520 + i] = v;
    }
}

// ---------------------------------------------------------------------------
// Branch-free count of { thr[t] <= xs } over 64 sorted entries (7 LDS).
// ---------------------------------------------------------------------------
__device__ __forceinline__ int seg_search(const float* __restrict__ thrp, float xs)
{
    int p = (thrp[31] <= xs) ? 32 : 0;
    p += (thrp[p + 15] <= xs) ? 16 : 0;
    p += (thrp[p + 7]  <= xs) ? 8  : 0;
    p += (thrp[p + 3]  <= xs) ? 4  : 0;
    p += (thrp[p + 1]  <= xs) ? 2  : 0;
    p += (thrp[p]      <= xs) ? 1  : 0;
    return p + ((thrp[p] <= xs) ? 1 : 0);   // in [0,64]
}

// ---------------------------------------------------------------------------
// Kernel 2: evaluation. Block = 4 features ("quad") x 512 rows, 256 threads.
// Warp owns 64 rows as 8 batches of 8. Phase 1: lane=(ff=lane>>3, rrow=lane&7)
// does 32 distinct searches; results exchanged via a 32-slot smem buffer
// (1 STS.64 + broadcast LDS.64 per r2 — replaces 16 SHFLs). Phase 2:
// lane=(ff,j=lane&7): LDS.64 fp16 table row chunk -> 2 FMA -> coalesced stcs.
// ---------------------------------------------------------------------------
__global__ void __launch_bounds__(256, 8) dfe_eval(
    const float* __restrict__ x, float* __restrict__ out)
{
    __shared__ h4     stab[4 * TAB_S];
    __shared__ float  sthr[4 * THR_S];
    __shared__ float2 sxch[8][32];     // per-warp (xs, seg) exchange

    int tid = threadIdx.x;
    int quad = blockIdx.x;
    int bbase = blockIdx.y * 512;

    #pragma unroll
    for (int ff = 0; ff < 4; ff++)
        for (int i = tid; i < 520; i += 256)
            stab[ff * TAB_S + i] = g_tab_h[(quad * 4 + ff) * 520 + i];
    for (int i = tid; i < 4 * 64; i += 256)
        sthr[(i >> 6) * THR_S + (i & 63)] = g_thr[quad * 256 + i];
    __syncthreads();

    int lane = tid & 31, w = tid >> 5;
    int rrow = lane & 7;       // phase-1 row within batch
    int ff   = lane >> 3;      // feature within quad (both phases)
    int j    = lane & 7;       // phase-2 e-pair

    const float* thrp = sthr + ff * THR_S;
    const h4*    tabf = stab + ff * TAB_S;
    float2*      xch  = sxch[w];

    int rb0 = bbase + w * 64;
    const float* xpb  = x   + (size_t)rb0 * FN + quad * 4 + ff;
    float*       outb = out + (size_t)rb0 * (FN * EN) + quad * 64 + ff * 16 + j * 2;

    float xs = __ldg(xpb + (size_t)rrow * FN);
    int   seg = seg_search(thrp, xs);

    #pragma unroll
    for (int batch = 0; batch < 8; batch++) {
        xch[lane] = make_float2(xs, __int_as_float(seg));
        __syncwarp();
        if (batch < 7)
            xs = __ldg(xpb + (size_t)((batch + 1) * 8 + rrow) * FN);

        float* orow = outb + (size_t)(batch * 8) * (FN * EN);
        #pragma unroll
        for (int r2 = 0; r2 < 8; r2++) {
            float2 e = xch[(lane & 24) | r2];   // slot of (rrow=r2, ff)
            int sg = __float_as_int(e.y);
            h4 v = tabf[sg * 8 + j];
            float2 a = __half22float2(v.a);
            float2 c = __half22float2(v.c);
            float2 o;
            o.x = fmaf(a.x, e.x, c.x);
            o.y = fmaf(a.y, e.x, c.y);
            __stcs((float2*)(orow + (size_t)r2 * (FN * EN)), o);
        }

        if (batch < 7) seg = seg_search(thrp, xs);
        __syncwarp();   // protect xch before next overwrite
    }
}

extern "C" void kernel_launch(void* const* d_in, const int* in_sizes, int n_in,
                              void* d_out, int out_size)
{
    const float* x  = (const float*)d_in[0];
    const float* W1 = (const float*)d_in[1];
    const float* b1 = (const float*)d_in[2];
    const float* W2 = (const float*)d_in[3];
    const float* b2 = (const float*)d_in[4];
    float* out = (float*)d_out;

    dfe_precompute<<<FN, 128>>>(W1, b1, W2, b2);
    dfe_eval<<<dim3(FN / 4, BN / 512), 256>>>(x, out);
}